// round 15
// baseline (speedup 1.0000x reference)
#include <cuda_runtime.h>

// Problem constants
#define NSEG   7
#define NSUBS  4
#define NEVAL  (NSEG*NSUBS*3)   // 84 hypernet evaluations (seg, sub, stage)
#define NROW   128              // WIDTH
#define QROW   32               // rows per lane-quarter
#define ROWF   20               // floats per table row: Wpair[8], Upair[8], B, 0, -c, -c
#define TABF   (NROW*ROWF)      // 2560 floats = 10KB per table
#define NPTS   65536
#define LPOFF  (8*NPTS*8)       // zt occupies first 8*N*8 floats, then logp 8*N

__device__ float g_tab[NEVAL * TABF];   // 860 KB precomputed hypernet tables

typedef unsigned long long u64;

// ---------------- f32x2 packed helpers ----------------
static __device__ __forceinline__ u64 pk2(float a, float b){
    u64 r; asm("mov.b64 %0, {%1, %2};" : "=l"(r) : "f"(a), "f"(b)); return r;
}
static __device__ __forceinline__ void upk2(u64 v, float& a, float& b){
    asm("mov.b64 {%0, %1}, %2;" : "=f"(a), "=f"(b) : "l"(v));
}
static __device__ __forceinline__ u64 ffma2(u64 a, u64 b, u64 c){
    u64 d; asm("fma.rn.f32x2 %0, %1, %2, %3;" : "=l"(d) : "l"(a), "l"(b), "l"(c)); return d;
}
static __device__ __forceinline__ u64 fadd2(u64 a, u64 b){
    u64 d; asm("add.rn.f32x2 %0, %1, %2;" : "=l"(d) : "l"(a), "l"(b)); return d;
}
static __device__ __forceinline__ u64 fmul2(u64 a, u64 b){
    u64 d; asm("mul.rn.f32x2 %0, %1, %2;" : "=l"(d) : "l"(a), "l"(b)); return d;
}
static __device__ __forceinline__ float tanh_approx(float x){
    float y; asm("tanh.approx.f32 %0, %1;" : "=f"(y) : "f"(x)); return y;
}
// 4-way quarter reduce: butterfly over lanes ^8 and ^16 (u64 payload)
static __device__ __forceinline__ u64 quad_reduce(u64 v){
    v = fadd2(v, __shfl_xor_sync(0xffffffffu, v, 8));
    v = fadd2(v, __shfl_xor_sync(0xffffffffu, v, 16));
    return v;
}

// ---------------- Hypernetwork: precompute (Wpairs, Upairs, B, -c) tables ----------------
// eval e -> seg = e/12, sub = (e%12)/3, stage = e%3 (0: t, 1: t+dt/2, 2: t+dt)
__global__ void hyper_kernel(const float* __restrict__ ts,
    const float* __restrict__ w1, const float* __restrict__ b1,
    const float* __restrict__ w2, const float* __restrict__ b2,
    const float* __restrict__ w3, const float* __restrict__ b3)
{
    __shared__ float h1s[64], h2s[64];
    const int e = blockIdx.x;
    const int tid = threadIdx.x;        // 128 threads
    const int seg = e / 12, r = e % 12, sub = r / 3, st = r % 3;

    float t0 = ts[seg], t1 = ts[seg+1];
    float dt = (t1 - t0) / 4.0f;
    float t = t0;
    for (int k = 0; k < sub; k++) t += dt;   // replicate reference's iterative t accumulation
    if      (st == 1) t += dt * 0.5f;
    else if (st == 2) t += dt;

    if (tid < 64) h1s[tid] = tanhf(w1[tid] * t + b1[tid]);
    __syncthreads();
    if (tid < 64) {
        float acc = b2[tid];
        const float* row = w2 + tid * 64;
        #pragma unroll 8
        for (int k = 0; k < 64; k++) acc += row[k] * h1s[k];
        h2s[tid] = tanhf(acc);
    }
    __syncthreads();

    const int i = tid;                  // output row 0..127
    float W[8], U[8];
    #pragma unroll
    for (int d = 0; d < 8; d++) {
        int mW = i*8 + d, mU = 1024 + i*8 + d, mG = 2048 + i*8 + d;
        float aw = b3[mW], au = b3[mU], ag = b3[mG];
        const float4* rw = (const float4*)(w3 + mW*64);
        const float4* ru = (const float4*)(w3 + mU*64);
        const float4* rg = (const float4*)(w3 + mG*64);
        #pragma unroll 4
        for (int k = 0; k < 16; k++) {
            float4 vw = rw[k], vu = ru[k], vg = rg[k];
            float hA = h2s[4*k], hB = h2s[4*k+1], hC = h2s[4*k+2], hD = h2s[4*k+3];
            aw += vw.x*hA + vw.y*hB + vw.z*hC + vw.w*hD;
            au += vu.x*hA + vu.y*hB + vu.z*hC + vu.w*hD;
            ag += vg.x*hA + vg.y*hB + vg.z*hC + vg.w*hD;
        }
        float sg = 1.0f / (1.0f + expf(-ag));
        W[d] = aw;
        U[d] = au * sg * (1.0f/128.0f);   // fold /WIDTH into U
    }
    int mB = 3072 + i;
    float ab = b3[mB];
    {
        const float4* rb = (const float4*)(w3 + mB*64);
        #pragma unroll 4
        for (int k = 0; k < 16; k++) {
            float4 v = rb[k];
            ab += v.x*h2s[4*k] + v.y*h2s[4*k+1] + v.z*h2s[4*k+2] + v.w*h2s[4*k+3];
        }
    }
    float c = 0.0f;                       // trace coefficient: sum_d W_d * (U_d/128)
    #pragma unroll
    for (int d = 0; d < 8; d++) c += W[d]*U[d];

    float* o = g_tab + (size_t)e*TABF + i*ROWF;
    #pragma unroll
    for (int d = 0; d < 8; d++) { o[d] = W[d]; o[8+d] = U[d]; }
    o[16] = ab; o[17] = 0.0f; o[18] = -c; o[19] = -c;
}

// ---------------- RHS partial: 2 samples per thread, QROW rows ----------------
// z[0..3] = sample A d-pairs, z[4..7] = sample B. tab pre-offset to this
// lane-quarter's row range. Result is the partial over QROW rows.
static __device__ __forceinline__ void rhs_partial(const float* __restrict__ tab,
                                                   const u64 z[8], u64 dz[8], u64& tr)
{
    #pragma unroll
    for (int d = 0; d < 8; d++) dz[d] = 0ULL;
    tr = 0ULL;

    #pragma unroll 4
    for (int i = 0; i < QROW; i++) {
        const ulonglong2* r = (const ulonglong2*)(tab + i*ROWF);
        ulonglong2 w0 = r[0], w1 = r[1];   // W pairs
        ulonglong2 u0 = r[2], u1 = r[3];   // U pairs
        ulonglong2 bc = r[4];              // (B, 0) | (-c, -c)

        // sample A dot: s = sum_d W_d z_d + B
        u64 sa = ffma2(w0.x, z[0], bc.x);
        u64 sb = fmul2(w1.x, z[2]);
        sa = ffma2(w0.y, z[1], sa);
        sb = ffma2(w1.y, z[3], sb);
        sa = fadd2(sa, sb);
        float ax, ay; upk2(sa, ax, ay);
        float hA = tanh_approx(ax + ay);

        // sample B dot
        u64 ta = ffma2(w0.x, z[4], bc.x);
        u64 tb = fmul2(w1.x, z[6]);
        ta = ffma2(w0.y, z[5], ta);
        tb = ffma2(w1.y, z[7], tb);
        ta = fadd2(ta, tb);
        float bx, by; upk2(ta, bx, by);
        float hB = tanh_approx(bx + by);

        u64 hA2 = pk2(hA, hA), hB2 = pk2(hB, hB);
        dz[0] = ffma2(hA2, u0.x, dz[0]);
        dz[1] = ffma2(hA2, u0.y, dz[1]);
        dz[2] = ffma2(hA2, u1.x, dz[2]);
        dz[3] = ffma2(hA2, u1.y, dz[3]);
        dz[4] = ffma2(hB2, u0.x, dz[4]);
        dz[5] = ffma2(hB2, u0.y, dz[5]);
        dz[6] = ffma2(hB2, u1.x, dz[6]);
        dz[7] = ffma2(hB2, u1.y, dz[7]);

        float gA = fmaf(hA, hA, -1.0f);           // h^2 - 1
        float gB = fmaf(hB, hB, -1.0f);
        tr = ffma2(pk2(gA, gB), bc.y, tr);        // += (1-h^2)*c  (trace)
    }
}

// ---------------- Main integration kernel ----------------
// Lane quartets {l, l^8, l^16, l^24} cooperate on the same 2 samples:
// quarter q = lane>>3 does rows [q*32,(q+1)*32). Partials reduced by a
// two-round shfl.xor butterfly — no barriers, no smem.
__global__ void __launch_bounds__(128) cnf_main(
    const float* __restrict__ ts, const float* __restrict__ z0,
    const float* __restrict__ lp0, float* __restrict__ out)
{
    __shared__ float stab[3*TABF];          // 30 KB: [E0 | M | E2] staged tables
    float* s0 = stab;
    float* s1 = stab + TABF;
    float* s2 = stab + 2*TABF;
    const int tid  = threadIdx.x;
    const int lane = tid & 31;
    const int wrp  = tid >> 5;
    const int q    = lane >> 3;             // which row quarter this lane computes
    const int li   = lane & 7;
    const int n0   = (blockIdx.x * 32 + wrp * 8 + li) * 2;
    const int rb   = q * QROW * ROWF;       // table row-base offset (floats)

    // load z for samples n0 (A), n0+1 (B); pack adjacent dims: z[k] = (z_{2k}, z_{2k+1})
    const float4* zv = (const float4*)(z0 + (size_t)n0*8);
    float4 p0 = zv[0], p1 = zv[1], p2 = zv[2], p3 = zv[3];
    u64 z[8];
    z[0]=pk2(p0.x,p0.y); z[1]=pk2(p0.z,p0.w); z[2]=pk2(p1.x,p1.y); z[3]=pk2(p1.z,p1.w);
    z[4]=pk2(p2.x,p2.y); z[5]=pk2(p2.z,p2.w); z[6]=pk2(p3.x,p3.y); z[7]=pk2(p3.z,p3.w);

    float lpa = lp0[n0], lpb = lp0[n0+1];
    u64 lp = pk2(lpa, lpb);

    // t = ts[0] output slice (quarter 0 only)
    if (q == 0) {
        float4* ov = (float4*)(out + (size_t)n0*8);
        ov[0]=p0; ov[1]=p1; ov[2]=p2; ov[3]=p3;
        out[LPOFF + n0]     = lpa;
        out[LPOFF + n0 + 1] = lpb;
    }

    const u64 M_TWO = pk2(2.0f, 2.0f);

    for (int seg = 0; seg < NSEG; seg++) {
        float t0 = ts[seg], t1 = ts[seg+1];
        float dt  = (t1 - t0) / 4.0f;
        float hdt = dt * 0.5f;
        float dt6 = dt / 6.0f;
        u64 DT = pk2(dt,dt), HDT = pk2(hdt,hdt), DT6 = pk2(dt6,dt6), NDT6 = pk2(-dt6,-dt6);

        for (int sub = 0; sub < NSUBS; sub++) {
            const int ev = (seg*NSUBS + sub)*3;

            // stage all 3 tables for this substep: E0 (k1), M (k2,k3), E2 (k4)
            __syncthreads();                      // protect prior substep's reads
            {
                const float4* src = (const float4*)(g_tab + (size_t)ev*TABF);
                float4* dst = (float4*)stab;
                #pragma unroll
                for (int j = tid; j < 3*TABF/4; j += 128) dst[j] = src[j];
            }
            __syncthreads();

            u64 kd[8], acc[8], zt[8], tr, trs;

            // ---- k1 @ t ----
            rhs_partial(s0 + rb, z, kd, tr);
            #pragma unroll
            for (int d = 0; d < 8; d++) kd[d] = quad_reduce(kd[d]);
            tr = quad_reduce(tr);
            trs = tr;
            #pragma unroll
            for (int d = 0; d < 8; d++) { acc[d] = kd[d]; zt[d] = ffma2(HDT, kd[d], z[d]); }

            // ---- k2 @ t+dt/2 ----
            rhs_partial(s1 + rb, zt, kd, tr);
            #pragma unroll
            for (int d = 0; d < 8; d++) kd[d] = quad_reduce(kd[d]);
            tr = quad_reduce(tr);
            trs = ffma2(M_TWO, tr, trs);
            #pragma unroll
            for (int d = 0; d < 8; d++) { acc[d] = ffma2(M_TWO, kd[d], acc[d]); zt[d] = ffma2(HDT, kd[d], z[d]); }

            // ---- k3 @ t+dt/2 ----
            rhs_partial(s1 + rb, zt, kd, tr);
            #pragma unroll
            for (int d = 0; d < 8; d++) kd[d] = quad_reduce(kd[d]);
            tr = quad_reduce(tr);
            trs = ffma2(M_TWO, tr, trs);
            #pragma unroll
            for (int d = 0; d < 8; d++) { acc[d] = ffma2(M_TWO, kd[d], acc[d]); zt[d] = ffma2(DT, kd[d], z[d]); }

            // ---- k4 @ t+dt ----
            rhs_partial(s2 + rb, zt, kd, tr);
            #pragma unroll
            for (int d = 0; d < 8; d++) kd[d] = quad_reduce(kd[d]);
            tr = quad_reduce(tr);
            trs = fadd2(trs, tr);
            #pragma unroll
            for (int d = 0; d < 8; d++) { acc[d] = fadd2(acc[d], kd[d]); z[d] = ffma2(DT6, acc[d], z[d]); }
            lp = ffma2(NDT6, trs, lp);                   // lp += dt/6 * (-(tr1+2tr2+2tr3+tr4))
        }

        // write slice seg+1 (quarter 0 only; all quarters hold identical state)
        if (q == 0) {
            float qq[16];
            upk2(z[0], qq[0],  qq[1]);  upk2(z[1], qq[2],  qq[3]);
            upk2(z[2], qq[4],  qq[5]);  upk2(z[3], qq[6],  qq[7]);
            upk2(z[4], qq[8],  qq[9]);  upk2(z[5], qq[10], qq[11]);
            upk2(z[6], qq[12], qq[13]); upk2(z[7], qq[14], qq[15]);
            float4* ov = (float4*)(out + (size_t)(seg+1)*NPTS*8 + (size_t)n0*8);
            ov[0] = make_float4(qq[0],  qq[1],  qq[2],  qq[3]);
            ov[1] = make_float4(qq[4],  qq[5],  qq[6],  qq[7]);
            ov[2] = make_float4(qq[8],  qq[9],  qq[10], qq[11]);
            ov[3] = make_float4(qq[12], qq[13], qq[14], qq[15]);
            float la, lb; upk2(lp, la, lb);
            out[LPOFF + (size_t)(seg+1)*NPTS + n0]     = la;
            out[LPOFF + (size_t)(seg+1)*NPTS + n0 + 1] = lb;
        }
    }
}

extern "C" void kernel_launch(void* const* d_in, const int* in_sizes, int n_in,
                              void* d_out, int out_size) {
    const float* ts  = (const float*)d_in[0];
    const float* z0  = (const float*)d_in[1];
    const float* lp0 = (const float*)d_in[2];
    const float* w1  = (const float*)d_in[3];
    const float* b1  = (const float*)d_in[4];
    const float* w2  = (const float*)d_in[5];
    const float* b2  = (const float*)d_in[6];
    const float* w3  = (const float*)d_in[7];
    const float* b3  = (const float*)d_in[8];
    float* out = (float*)d_out;

    hyper_kernel<<<NEVAL, 128>>>(ts, w1, b1, w2, b2, w3, b3);
    cnf_main<<<NPTS/64, 128>>>(ts, z0, lp0, out);
}